// round 5
// baseline (speedup 1.0000x reference)
#include <cuda_runtime.h>

// Involution (B=8, H=W=192, C=64, G=4, K=3, R=4 -> cr=16)
// Fused: kernel-gen (1x1 conv -> BN -> ReLU -> 1x1 conv) + 3x3 grouped dynamic filter.

#define HH 192
#define WW 192
#define CC 64
#define CR 16
#define GG 4
#define KK 3
#define TAPS 9

constexpr int TILE = 16;            // output tile edge per block
constexpr int HALO = TILE + 2;      // 18
constexpr int PIX_STRIDE = 17;      // float4 per pixel in smem (16 data + 1 pad -> conflict-free .128)
constexpr int TILE_F4 = HALO * HALO * PIX_STRIDE;          // 5508 float4
constexpr int W1_F4 = 256;          // [c4=16][d=16] float4 over 4 channels
constexpr int W2_F4 = 144;          // [d=16][tap=9] float4 over 4 groups
constexpr int B2_F4 = 9;
constexpr int SMEM_BYTES = (TILE_F4 + W1_F4 + W2_F4 + B2_F4) * 16 + 32 * 4; // 94800 B

__global__ __launch_bounds__(256, 2)
void involution_fused_kernel(const float* __restrict__ x,
                             const float* __restrict__ w1,
                             const float* __restrict__ b1,
                             const float* __restrict__ gamma,
                             const float* __restrict__ beta,
                             const float* __restrict__ mean,
                             const float* __restrict__ var,
                             const float* __restrict__ w2,
                             const float* __restrict__ b2,
                             float* __restrict__ out) {
    extern __shared__ float4 sm4[];
    float4* tile4 = sm4;                      // [18*18 pixels][17 f4]
    float4* w1f4  = sm4 + TILE_F4;            // [c4*16 + d]
    float4* w2f4  = w1f4 + W1_F4;             // [d*9 + tap]
    float4* b2f4  = w2f4 + W2_F4;             // [tap]
    float*  b1f   = (float*)(b2f4 + B2_F4);   // [16]
    float*  kbn   = b1f + 16;                 // [16]

    const int tid = threadIdx.x;
    const int gx0 = blockIdx.x * TILE;
    const int gy0 = blockIdx.y * TILE;
    const int bz  = blockIdx.z;

    // ---- fold BN into the first 1x1 conv ----
    if (tid < 16) {
        float s = gamma[tid] * rsqrtf(var[tid] + 1e-3f);
        kbn[tid] = s;
        b1f[tid] = (b1[tid] - mean[tid]) * s + beta[tid];
    }
    __syncthreads();

    // ---- stage fused weights into smem ----
    {
        // w1: [C=64][cr=16] row-major; build float4 over 4 consecutive input channels
        int d  = tid & 15;
        int c4 = tid >> 4;
        float s = kbn[d];
        w1f4[tid] = make_float4(w1[(4 * c4 + 0) * CR + d] * s,
                                w1[(4 * c4 + 1) * CR + d] * s,
                                w1[(4 * c4 + 2) * CR + d] * s,
                                w1[(4 * c4 + 3) * CR + d] * s);
        // w2: [cr=16][K*K*G=36] row-major; e = tap*4 + g -> float4 over g is contiguous
        if (tid < W2_F4) w2f4[tid] = ((const float4*)w2)[tid];
        if (tid < B2_F4) b2f4[tid] = ((const float4*)b2)[tid];
    }

    // ---- load 18x18 halo tile (zero-padded SAME) ----
    const float* xb = x + (size_t)bz * ((size_t)HH * WW * CC);
    #pragma unroll 2
    for (int s = tid; s < HALO * HALO * 16; s += 256) {
        int u   = s & 15;
        int pix = s >> 4;
        int py  = pix / HALO;
        int px  = pix - py * HALO;
        int gh  = gy0 - 1 + py;
        int gw  = gx0 - 1 + px;
        float4 v = make_float4(0.f, 0.f, 0.f, 0.f);
        if ((unsigned)gh < HH && (unsigned)gw < WW)
            v = ((const float4*)(xb + ((size_t)gh * WW + gw) * CC))[u];
        tile4[pix * PIX_STRIDE + u] = v;
    }
    __syncthreads();

    const int tx = tid & 15;
    const int ty = tid >> 4;
    const int pc = (ty + 1) * HALO + (tx + 1);

    // ---- phase B: t[d] = relu( x . w1' + b1' ), d = 0..15 ----
    float t[CR];
    #pragma unroll
    for (int d = 0; d < CR; d++) t[d] = b1f[d];

    const float4* xc = tile4 + pc * PIX_STRIDE;
    #pragma unroll
    for (int c4 = 0; c4 < 16; c4++) {
        float4 xv = xc[c4];
        const float4* wr = w1f4 + c4 * 16;
        #pragma unroll
        for (int d = 0; d < CR; d++) {
            float4 w = wr[d];
            t[d] = fmaf(xv.x, w.x, fmaf(xv.y, w.y, fmaf(xv.z, w.z, fmaf(xv.w, w.w, t[d]))));
        }
    }
    #pragma unroll
    for (int d = 0; d < CR; d++) t[d] = fmaxf(t[d], 0.f);

    // ---- phase C: kern[tap].{xyzw} = b2 + t . w2  (float4 over 4 groups) ----
    float4 kern[TAPS];
    #pragma unroll
    for (int tap = 0; tap < TAPS; tap++) kern[tap] = b2f4[tap];
    #pragma unroll
    for (int d = 0; d < CR; d++) {
        float td = t[d];
        const float4* wr = w2f4 + d * TAPS;
        #pragma unroll
        for (int tap = 0; tap < TAPS; tap++) {
            float4 w = wr[tap];
            kern[tap].x = fmaf(td, w.x, kern[tap].x);
            kern[tap].y = fmaf(td, w.y, kern[tap].y);
            kern[tap].z = fmaf(td, w.z, kern[tap].z);
            kern[tap].w = fmaf(td, w.w, kern[tap].w);
        }
    }

    // ---- phase D: out[c] = sum_tap kern[tap, c%4] * x[p+tap, c] ----
    // channels 4u..4u+3 cover groups (0,1,2,3) -> plain float4 componentwise FMA
    float4* outp = (float4*)(out +
        ((((size_t)bz * HH + (gy0 + ty)) * WW + (gx0 + tx)) * CC));
    #pragma unroll
    for (int u = 0; u < 16; u++) {
        float4 acc = make_float4(0.f, 0.f, 0.f, 0.f);
        #pragma unroll
        for (int tap = 0; tap < TAPS; tap++) {
            int di = tap / 3;
            int dj = tap - di * 3;
            float4 xv = tile4[((ty + di) * HALO + (tx + dj)) * PIX_STRIDE + u];
            float4 kw = kern[tap];
            acc.x = fmaf(kw.x, xv.x, acc.x);
            acc.y = fmaf(kw.y, xv.y, acc.y);
            acc.z = fmaf(kw.z, xv.z, acc.z);
            acc.w = fmaf(kw.w, xv.w, acc.w);
        }
        outp[u] = acc;
    }
}

extern "C" void kernel_launch(void* const* d_in, const int* in_sizes, int n_in,
                              void* d_out, int out_size) {
    const float* x     = (const float*)d_in[0];
    const float* w1    = (const float*)d_in[1];
    const float* b1    = (const float*)d_in[2];
    const float* gamma = (const float*)d_in[3];
    const float* beta  = (const float*)d_in[4];
    const float* mean  = (const float*)d_in[5];
    const float* var   = (const float*)d_in[6];
    const float* w2    = (const float*)d_in[7];
    const float* b2    = (const float*)d_in[8];
    float* out = (float*)d_out;

    int B = in_sizes[0] / (HH * WW * CC);

    static bool attr_set = false;
    if (!attr_set) {
        cudaFuncSetAttribute(involution_fused_kernel,
                             cudaFuncAttributeMaxDynamicSharedMemorySize, SMEM_BYTES);
        attr_set = true;
    }

    dim3 grid(WW / TILE, HH / TILE, B);   // 12 x 12 x 8
    dim3 block(256);
    involution_fused_kernel<<<grid, block, SMEM_BYTES>>>(
        x, w1, b1, gamma, beta, mean, var, w2, b2, out);
}

// round 6
// speedup vs baseline: 1.0222x; 1.0222x over previous
#include <cuda_runtime.h>

// Involution (B=8, H=W=192, C=64, G=4, K=3, R=4 -> cr=16)
// R6: 128 threads/block, 16x16 tile, 2 vertical pixels/thread,
// channel-split smem tile (8 f4/pixel, two passes) -> 53.3 KB smem, 4 blocks/SM.

#define HH 192
#define WW 192
#define CC 64
#define CR 16
#define TAPS 9

constexpr int TILE = 16;
constexpr int HALO = 18;
constexpr int PSTR = 9;                               // f4 per pixel (8 data + 1 pad)
constexpr int TILE_F4 = HALO * HALO * PSTR;           // 2916
constexpr int W1_F4 = 256;
constexpr int W2_F4 = 144;
constexpr int B2_F4 = 9;
constexpr int SMEM_BYTES = (TILE_F4 + W1_F4 + W2_F4 + B2_F4) * 16 + 32 * 4; // 53328 B

__device__ __forceinline__ void fma4(float4& a, const float4& k, const float4& v) {
    a.x = fmaf(k.x, v.x, a.x);
    a.y = fmaf(k.y, v.y, a.y);
    a.z = fmaf(k.z, v.z, a.z);
    a.w = fmaf(k.w, v.w, a.w);
}

__global__ __launch_bounds__(128, 4)
void involution_fused_kernel(const float* __restrict__ x,
                             const float* __restrict__ w1,
                             const float* __restrict__ b1,
                             const float* __restrict__ gamma,
                             const float* __restrict__ beta,
                             const float* __restrict__ mean,
                             const float* __restrict__ var,
                             const float* __restrict__ w2,
                             const float* __restrict__ b2,
                             float* __restrict__ out) {
    extern __shared__ float4 sm4[];
    float4* tile4 = sm4;                      // [18*18 px][9 f4]
    float4* w1f4  = sm4 + TILE_F4;            // [c4*16 + d], BN pre-folded
    float4* w2f4  = w1f4 + W1_F4;             // [d*9 + tap]
    float4* b2f4  = w2f4 + W2_F4;
    float*  b1f   = (float*)(b2f4 + B2_F4);   // [16] folded bias
    float*  kbn   = b1f + 16;                 // [16] BN scale

    const int tid = threadIdx.x;              // 0..127
    const int tx  = tid & 15;
    const int tyy = tid >> 4;                 // 0..7 -> output rows 2*tyy, 2*tyy+1
    const int gx0 = blockIdx.x * TILE;
    const int gy0 = blockIdx.y * TILE;
    const int bz  = blockIdx.z;

    if (tid < 16) {
        float s = gamma[tid] * rsqrtf(var[tid] + 1e-3f);
        kbn[tid] = s;
        b1f[tid] = (b1[tid] - mean[tid]) * s + beta[tid];
    }
    __syncthreads();

    #pragma unroll
    for (int i = tid; i < W1_F4; i += 128) {
        int d  = i & 15;
        int c4 = i >> 4;
        float s = kbn[d];
        w1f4[i] = make_float4(w1[(4 * c4 + 0) * CR + d] * s,
                              w1[(4 * c4 + 1) * CR + d] * s,
                              w1[(4 * c4 + 2) * CR + d] * s,
                              w1[(4 * c4 + 3) * CR + d] * s);
    }
    #pragma unroll
    for (int i = tid; i < W2_F4; i += 128) w2f4[i] = ((const float4*)w2)[i];
    if (tid < B2_F4) b2f4[tid] = ((const float4*)b2)[tid];

    const float* xb = x + (size_t)bz * ((size_t)HH * WW * CC);

    // ---- load tile half u0-7 (zero-padded SAME) ----
    #pragma unroll 2
    for (int s = tid; s < HALO * HALO * 8; s += 128) {
        int u   = s & 7;
        int pix = s >> 3;
        int py  = pix / HALO;
        int px  = pix - py * HALO;
        int gh  = gy0 - 1 + py;
        int gw  = gx0 - 1 + px;
        float4 v = make_float4(0.f, 0.f, 0.f, 0.f);
        if ((unsigned)gh < HH && (unsigned)gw < WW)
            v = ((const float4*)(xb + ((size_t)gh * WW + gw) * CC))[u];
        tile4[pix * PSTR + u] = v;
    }
    __syncthreads();

    // ---- phase B: t_p[d] = relu(x_p . w1' + b1'), two pixels per thread ----
    const int pc0 = (2 * tyy + 1) * HALO + (tx + 1);
    const int pc1 = pc0 + HALO;
    const float4* g0 = (const float4*)(xb + ((size_t)(gy0 + 2 * tyy)     * WW + gx0 + tx) * CC);
    const float4* g1 = (const float4*)(xb + ((size_t)(gy0 + 2 * tyy + 1) * WW + gx0 + tx) * CC);

    float t0[CR], t1[CR];
    #pragma unroll
    for (int d = 0; d < CR; d++) { t0[d] = b1f[d]; t1[d] = b1f[d]; }

    const float4* xc0 = tile4 + pc0 * PSTR;
    const float4* xc1 = tile4 + pc1 * PSTR;
    #pragma unroll
    for (int c4 = 0; c4 < 8; c4++) {               // first channel half from smem
        float4 x0 = xc0[c4];
        float4 x1 = xc1[c4];
        const float4* wr = w1f4 + c4 * 16;
        #pragma unroll
        for (int d = 0; d < CR; d++) {
            float4 w = wr[d];
            t0[d] = fmaf(x0.x, w.x, fmaf(x0.y, w.y, fmaf(x0.z, w.z, fmaf(x0.w, w.w, t0[d]))));
            t1[d] = fmaf(x1.x, w.x, fmaf(x1.y, w.y, fmaf(x1.z, w.z, fmaf(x1.w, w.w, t1[d]))));
        }
    }
    #pragma unroll
    for (int c4 = 8; c4 < 16; c4++) {              // second channel half from global
        float4 x0 = g0[c4];
        float4 x1 = g1[c4];
        const float4* wr = w1f4 + c4 * 16;
        #pragma unroll
        for (int d = 0; d < CR; d++) {
            float4 w = wr[d];
            t0[d] = fmaf(x0.x, w.x, fmaf(x0.y, w.y, fmaf(x0.z, w.z, fmaf(x0.w, w.w, t0[d]))));
            t1[d] = fmaf(x1.x, w.x, fmaf(x1.y, w.y, fmaf(x1.z, w.z, fmaf(x1.w, w.w, t1[d]))));
        }
    }
    #pragma unroll
    for (int d = 0; d < CR; d++) { t0[d] = fmaxf(t0[d], 0.f); t1[d] = fmaxf(t1[d], 0.f); }

    // ---- phase C: per-pixel 3x3 kernels (f4 over groups), weights amortized x2 ----
    float4 k0[TAPS], k1[TAPS];
    #pragma unroll
    for (int tap = 0; tap < TAPS; tap++) { k0[tap] = b2f4[tap]; k1[tap] = b2f4[tap]; }
    #pragma unroll
    for (int d = 0; d < CR; d++) {
        float a = t0[d], b = t1[d];
        const float4* wr = w2f4 + d * TAPS;
        #pragma unroll
        for (int tap = 0; tap < TAPS; tap++) {
            float4 w = wr[tap];
            k0[tap].x = fmaf(a, w.x, k0[tap].x); k0[tap].y = fmaf(a, w.y, k0[tap].y);
            k0[tap].z = fmaf(a, w.z, k0[tap].z); k0[tap].w = fmaf(a, w.w, k0[tap].w);
            k1[tap].x = fmaf(b, w.x, k1[tap].x); k1[tap].y = fmaf(b, w.y, k1[tap].y);
            k1[tap].z = fmaf(b, w.z, k1[tap].z); k1[tap].w = fmaf(b, w.w, k1[tap].w);
        }
    }

    // ---- phase D: two channel-half passes; 4 rows serve 2 outputs ----
    float4* o0 = (float4*)(out + (((size_t)bz * HH + gy0 + 2 * tyy)     * WW + gx0 + tx) * CC);
    float4* o1 = (float4*)(out + (((size_t)bz * HH + gy0 + 2 * tyy + 1) * WW + gx0 + tx) * CC);
    const int rowstep = HALO * PSTR;
    const float4* base = tile4 + (2 * tyy * HALO + tx) * PSTR;

    #pragma unroll
    for (int uh = 0; uh < 2; uh++) {
        if (uh) {
            __syncthreads();
            #pragma unroll 2
            for (int s = tid; s < HALO * HALO * 8; s += 128) {
                int u   = s & 7;
                int pix = s >> 3;
                int py  = pix / HALO;
                int px  = pix - py * HALO;
                int gh  = gy0 - 1 + py;
                int gw  = gx0 - 1 + px;
                float4 v = make_float4(0.f, 0.f, 0.f, 0.f);
                if ((unsigned)gh < HH && (unsigned)gw < WW)
                    v = ((const float4*)(xb + ((size_t)gh * WW + gw) * CC))[8 + u];
                tile4[pix * PSTR + u] = v;
            }
            __syncthreads();
        }
        #pragma unroll 2
        for (int u = 0; u < 8; u++) {
            float4 a0 = make_float4(0.f, 0.f, 0.f, 0.f);
            float4 a1 = make_float4(0.f, 0.f, 0.f, 0.f);
            #pragma unroll
            for (int dj = 0; dj < 3; dj++) {
                const float4* col = base + dj * PSTR + u;
                float4 r0 = col[0];
                float4 r1 = col[rowstep];
                float4 r2 = col[2 * rowstep];
                float4 r3 = col[3 * rowstep];
                fma4(a0, k0[dj],     r0);
                fma4(a0, k0[3 + dj], r1);
                fma4(a0, k0[6 + dj], r2);
                fma4(a1, k1[dj],     r1);
                fma4(a1, k1[3 + dj], r2);
                fma4(a1, k1[6 + dj], r3);
            }
            o0[uh * 8 + u] = a0;
            o1[uh * 8 + u] = a1;
        }
    }
}

extern "C" void kernel_launch(void* const* d_in, const int* in_sizes, int n_in,
                              void* d_out, int out_size) {
    const float* x     = (const float*)d_in[0];
    const float* w1    = (const float*)d_in[1];
    const float* b1    = (const float*)d_in[2];
    const float* gamma = (const float*)d_in[3];
    const float* beta  = (const float*)d_in[4];
    const float* mean  = (const float*)d_in[5];
    const float* var   = (const float*)d_in[6];
    const float* w2    = (const float*)d_in[7];
    const float* b2    = (const float*)d_in[8];
    float* out = (float*)d_out;

    int B = in_sizes[0] / (HH * WW * CC);

    static bool attr_set = false;
    if (!attr_set) {
        cudaFuncSetAttribute(involution_fused_kernel,
                             cudaFuncAttributeMaxDynamicSharedMemorySize, SMEM_BYTES);
        attr_set = true;
    }

    dim3 grid(WW / TILE, HH / TILE, B);   // 12 x 12 x 8
    dim3 block(128);
    involution_fused_kernel<<<grid, block, SMEM_BYTES>>>(
        x, w1, b1, gamma, beta, mean, var, w2, b2, out);
}

// round 7
// speedup vs baseline: 1.1192x; 1.0948x over previous
#include <cuda_runtime.h>

// Involution (B=8, H=W=192, C=64, G=4, K=3, R=4 -> cr=16)
// R7: weights in __constant__ (LDCU path, off L1tex), tile-only smem (46.7 KB),
// 128 threads/block, 16x16 tile, 2 vertical px/thread, channel-split two passes.

#define HH 192
#define WW 192
#define CC 64
#define CR 16
#define TAPS 9

constexpr int TILE = 16;
constexpr int HALO = 18;
constexpr int PSTR = 9;                               // f4 per pixel (8 data + 1 pad)
constexpr int TILE_F4 = HALO * HALO * PSTR;           // 2916
constexpr int SMEM_BYTES = TILE_F4 * 16;              // 46656 B

struct ConstW {
    float4 w1[256];   // [c4=16][d=16], BN folded
    float4 w2[144];   // [d=16][tap=9], f4 over 4 groups
    float4 b2[9];
    float  b1[16];    // BN-folded bias
};
__constant__ ConstW cW;
__device__ ConstW scratchW;

__global__ void involution_prep_kernel(const float* __restrict__ w1,
                                       const float* __restrict__ b1,
                                       const float* __restrict__ gamma,
                                       const float* __restrict__ beta,
                                       const float* __restrict__ mean,
                                       const float* __restrict__ var,
                                       const float* __restrict__ w2,
                                       const float* __restrict__ b2) {
    __shared__ float s[16];
    int tid = threadIdx.x;   // 256 threads
    if (tid < 16) {
        float sc = gamma[tid] * rsqrtf(var[tid] + 1e-3f);
        s[tid] = sc;
        scratchW.b1[tid] = (b1[tid] - mean[tid]) * sc + beta[tid];
    }
    __syncthreads();
    {
        int d  = tid & 15;
        int c4 = tid >> 4;
        float sc = s[d];
        scratchW.w1[tid] = make_float4(w1[(4 * c4 + 0) * CR + d] * sc,
                                       w1[(4 * c4 + 1) * CR + d] * sc,
                                       w1[(4 * c4 + 2) * CR + d] * sc,
                                       w1[(4 * c4 + 3) * CR + d] * sc);
    }
    if (tid < 144) scratchW.w2[tid] = ((const float4*)w2)[tid];
    if (tid < 9)   scratchW.b2[tid] = ((const float4*)b2)[tid];
}

__device__ __forceinline__ void fma4(float4& a, const float4& k, const float4& v) {
    a.x = fmaf(k.x, v.x, a.x);
    a.y = fmaf(k.y, v.y, a.y);
    a.z = fmaf(k.z, v.z, a.z);
    a.w = fmaf(k.w, v.w, a.w);
}

__global__ __launch_bounds__(128, 4)
void involution_fused_kernel(const float* __restrict__ x,
                             float* __restrict__ out) {
    extern __shared__ float4 tile4[];         // [18*18 px][9 f4]

    const int tid = threadIdx.x;              // 0..127
    const int tx  = tid & 15;
    const int tyy = tid >> 4;                 // 0..7 -> output rows 2*tyy, 2*tyy+1
    const int gx0 = blockIdx.x * TILE;
    const int gy0 = blockIdx.y * TILE;
    const int bz  = blockIdx.z;

    const float* xb = x + (size_t)bz * ((size_t)HH * WW * CC);

    // ---- load tile channel-half u0-7 (zero-padded SAME) ----
    #pragma unroll 2
    for (int s = tid; s < HALO * HALO * 8; s += 128) {
        int u   = s & 7;
        int pix = s >> 3;
        int py  = pix / HALO;
        int px  = pix - py * HALO;
        int gh  = gy0 - 1 + py;
        int gw  = gx0 - 1 + px;
        float4 v = make_float4(0.f, 0.f, 0.f, 0.f);
        if ((unsigned)gh < HH && (unsigned)gw < WW)
            v = ((const float4*)(xb + ((size_t)gh * WW + gw) * CC))[u];
        tile4[pix * PSTR + u] = v;
    }
    __syncthreads();

    // ---- phase B: t_p[d] = relu(x_p . w1' + b1'), two pixels per thread ----
    const int pc0 = (2 * tyy + 1) * HALO + (tx + 1);
    const int pc1 = pc0 + HALO;
    const float4* g0 = (const float4*)(xb + ((size_t)(gy0 + 2 * tyy)     * WW + gx0 + tx) * CC);
    const float4* g1 = (const float4*)(xb + ((size_t)(gy0 + 2 * tyy + 1) * WW + gx0 + tx) * CC);

    float t0[CR], t1[CR];
    #pragma unroll
    for (int d = 0; d < CR; d++) { t0[d] = cW.b1[d]; t1[d] = cW.b1[d]; }

    const float4* xc0 = tile4 + pc0 * PSTR;
    const float4* xc1 = tile4 + pc1 * PSTR;
    #pragma unroll
    for (int c4 = 0; c4 < 8; c4++) {               // first channel half from smem
        float4 x0 = xc0[c4];
        float4 x1 = xc1[c4];
        #pragma unroll
        for (int d = 0; d < CR; d++) {
            float4 w = cW.w1[c4 * 16 + d];
            t0[d] = fmaf(x0.x, w.x, fmaf(x0.y, w.y, fmaf(x0.z, w.z, fmaf(x0.w, w.w, t0[d]))));
            t1[d] = fmaf(x1.x, w.x, fmaf(x1.y, w.y, fmaf(x1.z, w.z, fmaf(x1.w, w.w, t1[d]))));
        }
    }
    #pragma unroll
    for (int c4 = 8; c4 < 16; c4++) {              // second channel half from global
        float4 x0 = g0[c4];
        float4 x1 = g1[c4];
        #pragma unroll
        for (int d = 0; d < CR; d++) {
            float4 w = cW.w1[c4 * 16 + d];
            t0[d] = fmaf(x0.x, w.x, fmaf(x0.y, w.y, fmaf(x0.z, w.z, fmaf(x0.w, w.w, t0[d]))));
            t1[d] = fmaf(x1.x, w.x, fmaf(x1.y, w.y, fmaf(x1.z, w.z, fmaf(x1.w, w.w, t1[d]))));
        }
    }
    #pragma unroll
    for (int d = 0; d < CR; d++) { t0[d] = fmaxf(t0[d], 0.f); t1[d] = fmaxf(t1[d], 0.f); }

    // ---- phase C: per-pixel 3x3 kernels (f4 over groups) ----
    float4 k0[TAPS], k1[TAPS];
    #pragma unroll
    for (int tap = 0; tap < TAPS; tap++) { k0[tap] = cW.b2[tap]; k1[tap] = cW.b2[tap]; }
    #pragma unroll
    for (int d = 0; d < CR; d++) {
        float a = t0[d], b = t1[d];
        #pragma unroll
        for (int tap = 0; tap < TAPS; tap++) {
            float4 w = cW.w2[d * TAPS + tap];
            k0[tap].x = fmaf(a, w.x, k0[tap].x); k0[tap].y = fmaf(a, w.y, k0[tap].y);
            k0[tap].z = fmaf(a, w.z, k0[tap].z); k0[tap].w = fmaf(a, w.w, k0[tap].w);
            k1[tap].x = fmaf(b, w.x, k1[tap].x); k1[tap].y = fmaf(b, w.y, k1[tap].y);
            k1[tap].z = fmaf(b, w.z, k1[tap].z); k1[tap].w = fmaf(b, w.w, k1[tap].w);
        }
    }

    // ---- phase D: two channel-half passes; 4 smem rows serve 2 outputs ----
    float4* o0 = (float4*)(out + (((size_t)bz * HH + gy0 + 2 * tyy)     * WW + gx0 + tx) * CC);
    float4* o1 = (float4*)(out + (((size_t)bz * HH + gy0 + 2 * tyy + 1) * WW + gx0 + tx) * CC);
    const int rowstep = HALO * PSTR;
    const float4* base = tile4 + (2 * tyy * HALO + tx) * PSTR;

    #pragma unroll
    for (int uh = 0; uh < 2; uh++) {
        if (uh) {
            __syncthreads();
            #pragma unroll 2
            for (int s = tid; s < HALO * HALO * 8; s += 128) {
                int u   = s & 7;
                int pix = s >> 3;
                int py  = pix / HALO;
                int px  = pix - py * HALO;
                int gh  = gy0 - 1 + py;
                int gw  = gx0 - 1 + px;
                float4 v = make_float4(0.f, 0.f, 0.f, 0.f);
                if ((unsigned)gh < HH && (unsigned)gw < WW)
                    v = ((const float4*)(xb + ((size_t)gh * WW + gw) * CC))[8 + u];
                tile4[pix * PSTR + u] = v;
            }
            __syncthreads();
        }
        #pragma unroll 2
        for (int u = 0; u < 8; u++) {
            float4 a0 = make_float4(0.f, 0.f, 0.f, 0.f);
            float4 a1 = make_float4(0.f, 0.f, 0.f, 0.f);
            #pragma unroll
            for (int dj = 0; dj < 3; dj++) {
                const float4* col = base + dj * PSTR + u;
                float4 r0 = col[0];
                float4 r1 = col[rowstep];
                float4 r2 = col[2 * rowstep];
                float4 r3 = col[3 * rowstep];
                fma4(a0, k0[dj],     r0);
                fma4(a0, k0[3 + dj], r1);
                fma4(a0, k0[6 + dj], r2);
                fma4(a1, k1[dj],     r1);
                fma4(a1, k1[3 + dj], r2);
                fma4(a1, k1[6 + dj], r3);
            }
            o0[uh * 8 + u] = a0;
            o1[uh * 8 + u] = a1;
        }
    }
}

extern "C" void kernel_launch(void* const* d_in, const int* in_sizes, int n_in,
                              void* d_out, int out_size) {
    const float* x     = (const float*)d_in[0];
    const float* w1    = (const float*)d_in[1];
    const float* b1    = (const float*)d_in[2];
    const float* gamma = (const float*)d_in[3];
    const float* beta  = (const float*)d_in[4];
    const float* mean  = (const float*)d_in[5];
    const float* var   = (const float*)d_in[6];
    const float* w2    = (const float*)d_in[7];
    const float* b2    = (const float*)d_in[8];
    float* out = (float*)d_out;

    int B = in_sizes[0] / (HH * WW * CC);

    // 1) fold BN + stage weights into device scratch
    involution_prep_kernel<<<1, 256>>>(w1, b1, gamma, beta, mean, var, w2, b2);

    // 2) copy scratch -> __constant__ (D2D memcpy node, graph-capturable)
    static void* scratch_addr = nullptr;
    if (!scratch_addr) cudaGetSymbolAddress(&scratch_addr, scratchW);
    cudaMemcpyToSymbolAsync(cW, scratch_addr, sizeof(ConstW), 0,
                            cudaMemcpyDeviceToDevice, 0);

    // 3) main fused kernel
    dim3 grid(WW / TILE, HH / TILE, B);   // 12 x 12 x 8
    dim3 block(128);
    involution_fused_kernel<<<grid, block, SMEM_BYTES>>>(x, out);
}